// round 2
// baseline (speedup 1.0000x reference)
#include <cuda_runtime.h>
#include <math.h>

#define BQ 16
#define TQ 512
#define DQ 1024
#define FFQ 2048
#define EQ 4
#define CLSQ 1200
#define MQ (BQ*TQ)   // 8192

// ---------------- scratch (device globals; no allocation allowed) ------------
__device__ float g_h[(size_t)MQ * DQ];     // 32 MB  (fc1 out, then normed h)
__device__ float g_y1[(size_t)MQ * FFQ];   // 64 MB  (expert hidden, reused)
__device__ float g_moe[(size_t)MQ * DQ];   // 32 MB  (moe accumulation)
__device__ float g_gates[MQ * EQ];
__device__ float g_probs[MQ * EQ];
__device__ float g_sum[DQ];
__device__ float g_sumsq[DQ];
__device__ float g_scale[DQ];
__device__ float g_shift[DQ];

// ---------------- small helpers ---------------------------------------------
__device__ __forceinline__ float blockReduceSum256(float v, float* sh) {
    int tid = threadIdx.x;
    #pragma unroll
    for (int o = 16; o > 0; o >>= 1) v += __shfl_down_sync(0xffffffffu, v, o);
    if ((tid & 31) == 0) sh[tid >> 5] = v;
    __syncthreads();
    if (tid < 8) {
        float r = sh[tid];
        #pragma unroll
        for (int o = 4; o > 0; o >>= 1) r += __shfl_down_sync(0xffu, r, o);
        if (tid == 0) sh[0] = r;
    }
    __syncthreads();
    float r = sh[0];
    __syncthreads();
    return r;
}

__device__ __forceinline__ float blockReduceMax256(float v, float* sh) {
    int tid = threadIdx.x;
    #pragma unroll
    for (int o = 16; o > 0; o >>= 1) v = fmaxf(v, __shfl_down_sync(0xffffffffu, v, o));
    if ((tid & 31) == 0) sh[tid >> 5] = v;
    __syncthreads();
    if (tid < 8) {
        float r = sh[tid];
        #pragma unroll
        for (int o = 4; o > 0; o >>= 1) r = fmaxf(r, __shfl_down_sync(0xffu, r, o));
        if (tid == 0) sh[0] = r;
    }
    __syncthreads();
    float r = sh[0];
    __syncthreads();
    return r;
}

// ---------------- init: zero stats accumulators ------------------------------
__global__ void init_kernel() {
    int i = threadIdx.x;
    for (int d = i; d < DQ; d += 256) { g_sum[d] = 0.f; g_sumsq[d] = 0.f; }
}

// ---------------- generic conv/GEMM ------------------------------------------
// C[n, c] (epilogue) of sum_{kw, k} A[n + kw - KW/2 (within batch), k] * W[c, k, kw]
// W layout: [N][K][KW] row-major.  EPI: 0 = bias, 1 = relu(bias), 2 = moe accumulate
template<int KW, int EPI>
__global__ __launch_bounds__(256, 2)
void conv_gemm(const float* __restrict__ A, const float* __restrict__ W,
               const float* __restrict__ bias, float* __restrict__ C,
               const float* __restrict__ gates, int ecur, int accum,
               int N, int K)
{
    constexpr int HALO = KW / 2;
    constexpr int BM = 128, BN = 128, BK = 8;
    __shared__ float As[BK][BM + 2 * HALO + 2];   // +2 pad vs bank patterns
    __shared__ float Ws[KW][BK][BN];

    const int n0 = blockIdx.y * BM;
    const int c0 = blockIdx.x * BN;
    const int tid = threadIdx.x;
    const int ty = tid >> 4;          // 0..15 -> 8 rows each
    const int tx = tid & 15;          // 0..15 -> 8 cols each
    const int t_base = n0 % TQ;

    float acc[8][8];
    #pragma unroll
    for (int i = 0; i < 8; i++)
        #pragma unroll
        for (int j = 0; j < 8; j++) acc[i][j] = 0.f;

    for (int k0 = 0; k0 < K; k0 += BK) {
        // load A strip rows [n0-HALO, n0+BM-1+HALO]
        for (int i = tid; i < (BM + 2 * HALO) * BK; i += 256) {
            int s = i / BK, kk = i % BK;
            int t = t_base + s - HALO;
            float v = 0.f;
            if (t >= 0 && t < TQ)
                v = A[(size_t)(n0 + s - HALO) * K + k0 + kk];
            As[kk][s] = v;
        }
        // load W tile
        for (int i = tid; i < BN * BK * KW; i += 256) {
            int col = i / (BK * KW);
            int rem = i % (BK * KW);
            int kk = rem / KW, kw = rem % KW;
            int c = c0 + col;
            float w = 0.f;
            if (c < N) w = W[((size_t)c * K + k0 + kk) * KW + kw];
            Ws[kw][kk][col] = w;
        }
        __syncthreads();

        #pragma unroll
        for (int kk = 0; kk < BK; kk++) {
            float a[8 + 2 * HALO];
            #pragma unroll
            for (int i = 0; i < 8 + 2 * HALO; i++) a[i] = As[kk][ty * 8 + i];
            #pragma unroll
            for (int kw = 0; kw < KW; kw++) {
                float b[8];
                #pragma unroll
                for (int j = 0; j < 8; j++) b[j] = Ws[kw][kk][tx * 8 + j];
                #pragma unroll
                for (int i = 0; i < 8; i++)
                    #pragma unroll
                    for (int j = 0; j < 8; j++)
                        acc[i][j] = fmaf(a[i + kw], b[j], acc[i][j]);
            }
        }
        __syncthreads();
    }

    #pragma unroll
    for (int i = 0; i < 8; i++) {
        int n = n0 + ty * 8 + i;
        float g = 0.f;
        if (EPI == 2) g = gates[n * EQ + ecur];
        #pragma unroll
        for (int j = 0; j < 8; j++) {
            int c = c0 + tx * 8 + j;
            if (c < N) {
                float v = acc[i][j] + bias[c];
                if (EPI == 1) v = fmaxf(v, 0.f);
                size_t idx = (size_t)n * N + c;
                if (EPI == 2) {
                    v *= g;
                    if (accum) v += C[idx];
                }
                C[idx] = v;
            }
        }
    }
}

// ---------------- masked stats -----------------------------------------------
__global__ void stats_partial(const int* __restrict__ mask) {
    int d = blockIdx.y * 256 + threadIdx.x;
    int r0 = blockIdx.x * 256;
    float s = 0.f, s2 = 0.f;
    for (int r = 0; r < 256; r++) {
        int n = r0 + r;
        if (mask[n]) {
            float v = g_h[(size_t)n * DQ + d];
            s += v; s2 += v * v;
        }
    }
    atomicAdd(&g_sum[d], s);
    atomicAdd(&g_sumsq[d], s2);
}

__global__ void stats_final(const int* __restrict__ mask,
                            const float* __restrict__ bn_g,
                            const float* __restrict__ bn_b) {
    __shared__ float sh[32];
    __shared__ float s_cnt;
    int tid = threadIdx.x;  // 1024
    float c = 0.f;
    for (int n = tid; n < MQ; n += 1024) c += (float)mask[n];
    #pragma unroll
    for (int o = 16; o > 0; o >>= 1) c += __shfl_down_sync(0xffffffffu, c, o);
    if ((tid & 31) == 0) sh[tid >> 5] = c;
    __syncthreads();
    if (tid < 32) {
        c = sh[tid];
        #pragma unroll
        for (int o = 16; o > 0; o >>= 1) c += __shfl_down_sync(0xffffffffu, c, o);
        if (tid == 0) s_cnt = fmaxf(c, 1.f);
    }
    __syncthreads();
    float cnt = s_cnt;
    int d = tid;
    float mean = g_sum[d] / cnt;
    float var = g_sumsq[d] / cnt - mean * mean;
    var = fmaxf(var, 0.f);
    float sc = rsqrtf(var + 1e-5f) * bn_g[d];
    g_scale[d] = sc;
    g_shift[d] = bn_b[d] - mean * sc;
}

// ---------------- norm + relu + pe + gate ------------------------------------
__global__ void norm_gate(const int* __restrict__ mask,
                          const float* __restrict__ pe,
                          const float* __restrict__ gate_w) {
    int n = blockIdx.x;
    int t = n % TQ;
    int m = mask[n];
    int tid = threadIdx.x;
    float g0 = 0.f, g1 = 0.f, g2 = 0.f, g3 = 0.f;
    for (int d = tid; d < DQ; d += 256) {
        float v = g_h[(size_t)n * DQ + d];
        if (m) v = v * g_scale[d] + g_shift[d];
        v = fmaxf(v, 0.f) + pe[t * DQ + d];
        g_h[(size_t)n * DQ + d] = v;
        const float4 gw = *reinterpret_cast<const float4*>(gate_w + d * EQ);
        g0 += v * gw.x; g1 += v * gw.y; g2 += v * gw.z; g3 += v * gw.w;
    }
    __shared__ float sh[8][4];
    #pragma unroll
    for (int o = 16; o > 0; o >>= 1) {
        g0 += __shfl_down_sync(0xffffffffu, g0, o);
        g1 += __shfl_down_sync(0xffffffffu, g1, o);
        g2 += __shfl_down_sync(0xffffffffu, g2, o);
        g3 += __shfl_down_sync(0xffffffffu, g3, o);
    }
    if ((tid & 31) == 0) {
        int w = tid >> 5;
        sh[w][0] = g0; sh[w][1] = g1; sh[w][2] = g2; sh[w][3] = g3;
    }
    __syncthreads();
    if (tid == 0) {
        float l[4] = {0.f, 0.f, 0.f, 0.f};
        for (int w = 0; w < 8; w++)
            for (int e = 0; e < 4; e++) l[e] += sh[w][e];
        // dense softmax probs
        float mx = fmaxf(fmaxf(l[0], l[1]), fmaxf(l[2], l[3]));
        float ex[4], s = 0.f;
        for (int e = 0; e < 4; e++) { ex[e] = expf(l[e] - mx); s += ex[e]; }
        for (int e = 0; e < 4; e++) g_probs[n * EQ + e] = ex[e] / s;
        // top-2
        int i0 = 0;
        for (int e = 1; e < 4; e++) if (l[e] > l[i0]) i0 = e;
        int i1 = -1;
        for (int e = 0; e < 4; e++) {
            if (e == i0) continue;
            if (i1 < 0 || l[e] > l[i1]) i1 = e;
        }
        float ee = expf(l[i1] - l[i0]);
        float ga = 1.f / (1.f + ee);
        float gb = ee / (1.f + ee);
        float gt[4] = {0.f, 0.f, 0.f, 0.f};
        gt[i0] = ga; gt[i1] = gb;
        for (int e = 0; e < 4; e++) g_gates[n * EQ + e] = gt[e];
    }
}

// ---------------- LayerNorm + feat + feat_norm -------------------------------
__global__ void ln_kernel(const float* __restrict__ ln_g,
                          const float* __restrict__ ln_b,
                          float* __restrict__ feat,
                          float* __restrict__ featn) {
    __shared__ float sh[8];
    int n = blockIdx.x;
    int tid = threadIdx.x;
    float v[4];
    float s = 0.f;
    #pragma unroll
    for (int i = 0; i < 4; i++) {
        int d = tid + i * 256;
        v[i] = g_moe[(size_t)n * DQ + d];
        s += v[i];
    }
    float mu = blockReduceSum256(s, sh) * (1.f / DQ);
    float q = 0.f;
    #pragma unroll
    for (int i = 0; i < 4; i++) { float dd = v[i] - mu; q += dd * dd; }
    float var = blockReduceSum256(q, sh) * (1.f / DQ);
    float r = rsqrtf(var + 1e-6f);
    float f[4];
    float ss = 0.f;
    #pragma unroll
    for (int i = 0; i < 4; i++) {
        int d = tid + i * 256;
        f[i] = (v[i] - mu) * r * ln_g[d] + ln_b[d];
        feat[(size_t)n * DQ + d] = f[i];
        ss += f[i] * f[i];
    }
    float nrm = fmaxf(sqrtf(blockReduceSum256(ss, sh)), 1e-12f);
    float inv = 1.f / nrm;
    #pragma unroll
    for (int i = 0; i < 4; i++) {
        int d = tid + i * 256;
        featn[(size_t)n * DQ + d] = f[i] * inv;
    }
}

// ---------------- log-softmax over classes -----------------------------------
__global__ void softmax_kernel(const float* __restrict__ logits,
                               float* __restrict__ logp,
                               float* __restrict__ p) {
    __shared__ float sh[8];
    int n = blockIdx.x;
    int tid = threadIdx.x;
    const float* row = logits + (size_t)n * CLSQ;
    float mx = -1e30f;
    for (int c = tid; c < CLSQ; c += 256) mx = fmaxf(mx, row[c]);
    mx = blockReduceMax256(mx, sh);
    float s = 0.f;
    for (int c = tid; c < CLSQ; c += 256) s += expf(row[c] - mx);
    s = blockReduceSum256(s, sh);
    float lse = mx + logf(s);
    for (int c = tid; c < CLSQ; c += 256) {
        float lp = row[c] - lse;
        logp[(size_t)n * CLSQ + c] = lp;
        p[(size_t)n * CLSQ + c] = expf(lp);
    }
}

// ---------------- aux loss ---------------------------------------------------
__global__ void aux_kernel(float* __restrict__ out_aux) {
    __shared__ float sh[8];
    int tid = threadIdx.x;
    float imp[4] = {0.f, 0.f, 0.f, 0.f};
    float frc[4] = {0.f, 0.f, 0.f, 0.f};
    for (int n = tid; n < MQ; n += 256) {
        #pragma unroll
        for (int e = 0; e < 4; e++) {
            imp[e] += g_probs[n * EQ + e];
            frc[e] += (g_gates[n * EQ + e] > 0.f) ? 1.f : 0.f;
        }
    }
    float tot[8];
    #pragma unroll
    for (int e = 0; e < 4; e++) tot[e] = blockReduceSum256(imp[e], sh);
    #pragma unroll
    for (int e = 0; e < 4; e++) tot[4 + e] = blockReduceSum256(frc[e], sh);
    if (tid == 0) {
        float aux = 0.f;
        for (int e = 0; e < 4; e++)
            aux += (tot[4 + e] / (float)MQ) * (tot[e] / (float)MQ);
        out_aux[0] = (float)EQ * aux;
    }
}

// ---------------- host orchestration -----------------------------------------
extern "C" void kernel_launch(void* const* d_in, const int* in_sizes, int n_in,
                              void* d_out, int out_size) {
    const float* x      = (const float*)d_in[0];
    const int*   mask   = (const int*)  d_in[1];
    const float* fc1_w  = (const float*)d_in[2];
    const float* fc1_b  = (const float*)d_in[3];
    const float* bn_g   = (const float*)d_in[4];
    const float* bn_b   = (const float*)d_in[5];
    const float* pe     = (const float*)d_in[6];
    const float* gate_w = (const float*)d_in[7];
    const float* ew1    = (const float*)d_in[8];
    const float* eb1    = (const float*)d_in[9];
    const float* ew2    = (const float*)d_in[10];
    const float* eb2    = (const float*)d_in[11];
    const float* ln_g   = (const float*)d_in[12];
    const float* ln_b   = (const float*)d_in[13];
    const float* out_w  = (const float*)d_in[14];
    const float* out_b  = (const float*)d_in[15];

    float* out = (float*)d_out;
    const size_t FEAT = (size_t)MQ * DQ;       // 8388608
    const size_t LGT  = (size_t)MQ * CLSQ;     // 9830400
    float* feat   = out;
    float* featn  = out + FEAT;
    float* logits = out + 2 * FEAT;
    float* logp   = logits + LGT;
    float* p      = logp + LGT;
    float* aux    = p + LGT;

    float *h, *y1, *moe, *gates;
    cudaGetSymbolAddress((void**)&h,    g_h);
    cudaGetSymbolAddress((void**)&y1,   g_y1);
    cudaGetSymbolAddress((void**)&moe,  g_moe);
    cudaGetSymbolAddress((void**)&gates, g_gates);

    init_kernel<<<1, 256>>>();

    // fc1: h = x @ fc1_w^T + b
    conv_gemm<1, 0><<<dim3(DQ / 128, MQ / 128), 256>>>(
        x, fc1_w, fc1_b, h, nullptr, 0, 0, DQ, DQ);

    stats_partial<<<dim3(32, 4), 256>>>(mask);
    stats_final<<<1, 1024>>>(mask, bn_g, bn_b);
    norm_gate<<<MQ, 256>>>(mask, pe, gate_w);

    for (int e = 0; e < EQ; e++) {
        conv_gemm<3, 1><<<dim3(FFQ / 128, MQ / 128), 256>>>(
            h, ew1 + (size_t)e * FFQ * DQ * 3, eb1 + e * FFQ, y1,
            nullptr, 0, 0, FFQ, DQ);
        conv_gemm<3, 2><<<dim3(DQ / 128, MQ / 128), 256>>>(
            y1, ew2 + (size_t)e * DQ * FFQ * 3, eb2 + e * DQ, moe,
            gates, e, (e > 0) ? 1 : 0, DQ, FFQ);
    }

    ln_kernel<<<MQ, 256>>>(ln_g, ln_b, feat, featn);

    conv_gemm<1, 0><<<dim3((CLSQ + 127) / 128, MQ / 128), 256>>>(
        feat, out_w, out_b, logits, nullptr, 0, 0, CLSQ, DQ);

    softmax_kernel<<<MQ, 256>>>(logits, logp, p);
    aux_kernel<<<1, 256>>>(aux);
}